// round 14
// baseline (speedup 1.0000x reference)
#include <cuda_runtime.h>
#include <cstdint>

// FlowEmbedder cost, round 14: R13 (single 15-step forward-difference chain,
// sat-masks, s=0 fold, vote-gated steps 12-14) + packed early prologue:
//   DX/DY via packed FMA with {-1}, packed d^2 (bit-exact per lane, feeds the
//   unchanged scalar IEEE sqrt + Markstein floor path), packed H/G.
// ~12 fewer issue slots/thread; kernel is issue-count bound at ~60% eff.
//
// cost_i = 0.02*n_i + sum_{s=0}^{n_i-1} 0.08 * 2^{g_i(s)}
//   g(s) = k0 + k1 s + k2 s^2 + k3 s^3   (k's include -log2(e))
//   e(s+1)=e(s)*r(s); r(s+1)=r(s)*q(s); q(s+1)=q(s)*w
//   seeds: e0=0.08*2^{k0}, r0=2^{k1+k2+k3}, q0=2^{2k2+6k3}, w=2^{6k3}
// n_i = floor(euc/0.1)+1, euc/0.1 correctly rounded (fl(1/0.1f)==10.0f).

typedef unsigned long long u64;

__device__ __forceinline__ u64 pk2(float lo, float hi) {
    u64 r; asm("mov.b64 %0, {%1, %2};" : "=l"(r) : "f"(lo), "f"(hi)); return r;
}
__device__ __forceinline__ void upk2(float& lo, float& hi, u64 v) {
    asm("mov.b64 {%0, %1}, %2;" : "=f"(lo), "=f"(hi) : "l"(v));
}
__device__ __forceinline__ u64 mul2(u64 a, u64 b) {
    u64 d; asm("mul.rn.f32x2 %0, %1, %2;" : "=l"(d) : "l"(a), "l"(b)); return d;
}
__device__ __forceinline__ u64 add2(u64 a, u64 b) {
    u64 d; asm("add.rn.f32x2 %0, %1, %2;" : "=l"(d) : "l"(a), "l"(b)); return d;
}
__device__ __forceinline__ u64 fma2(u64 a, u64 b, u64 c) {
    u64 d; asm("fma.rn.f32x2 %0, %1, %2, %3;" : "=l"(d) : "l"(a), "l"(b), "l"(c)); return d;
}
__device__ __forceinline__ u64 ex2_2(u64 g) {
    float a, b; upk2(a, b, g);
    asm("ex2.approx.f32 %0, %1;" : "=f"(a) : "f"(a));
    asm("ex2.approx.f32 %0, %1;" : "=f"(b) : "f"(b));
    return pk2(a, b);
}
__device__ __forceinline__ float rsq_ap(float x) {
    float r; asm("rsqrt.approx.f32 %0, %1;" : "=f"(r) : "f"(x)); return r;
}

__global__ void __launch_bounds__(256)
flow_cost_kernel(const float4* __restrict__ x1,
                 const float4* __restrict__ x2,
                 const float* __restrict__ pp,
                 float* __restrict__ out,
                 int n_pairs) {
    int i = blockIdx.x * blockDim.x + threadIdx.x;  // 2 pairs per thread
    int base = 2 * i;
    if (base >= n_pairs) return;

    const float NL2E = -1.4426950408889634f;
    float p00 = NL2E * pp[0], p01 = NL2E * pp[1];
    float p10 = (3.0f * NL2E) * pp[2], p11 = (3.0f * NL2E) * pp[3];
    float p20 = (3.0f * NL2E) * pp[4], p21 = (3.0f * NL2E) * pp[5];
    u64 P00 = pk2(p00, p00), P01 = pk2(p01, p01);
    u64 P10 = pk2(p10, p10), P11 = pk2(p11, p11);
    u64 P20 = pk2(p20, p20), P21 = pk2(p21, p21);

    u64 X, Y, BX, BY;
    bool full = (base + 1 < n_pairs);
    if (full) {
        float4 a = x1[i];
        float4 b = x2[i];
        X  = pk2(a.x, a.z);  Y  = pk2(a.y, a.w);
        BX = pk2(b.x, b.z);  BY = pk2(b.y, b.w);
    } else {
        const float2* x1s = reinterpret_cast<const float2*>(x1);
        const float2* x2s = reinterpret_cast<const float2*>(x2);
        float2 a = x1s[base];
        float2 b = x2s[base];
        X  = pk2(a.x, a.x);  Y  = pk2(a.y, a.y);
        BX = pk2(b.x, b.x);  BY = pk2(b.y, b.y);
    }

    // ---- packed deltas and squared distance ---------------------------
    const u64 NEG1_2 = 0xBF800000BF800000ULL;   // {-1,-1}
    const u64 P01F_2 = 0x3DCCCCCD3DCCCCCDULL;   // {0.1f,0.1f}
    u64 DX = fma2(X, NEG1_2, BX);               // fl(bx - ax) per lane
    u64 DY = fma2(Y, NEG1_2, BY);
    u64 D2 = fma2(DX, DX, mul2(DY, DY));        // fl(fma(dx,dx,dy*dy))

    float d2_0, d2_1;
    upk2(d2_0, d2_1, D2);
    float euc0 = __fsqrt_rn(d2_0);              // IEEE, matches reference
    float euc1 = __fsqrt_rn(d2_1);

    // correctly-rounded euc/0.1 (== __fdiv_rn, fl(1/0.1f)==10.0f exactly)
    float t0 = euc0 * 10.0f;
    float nf0 = floorf(fmaf(fmaf(-0.1f, t0, euc0), 10.0f, t0)) + 1.0f;
    float t1 = euc1 * 10.0f;
    float nf1 = floorf(fmaf(fmaf(-0.1f, t1, euc1), 10.0f, t1)) + 1.0f;

    // warp-uniform max n (positive floats order as uint bit patterns)
    unsigned mk = __activemask();
    unsigned nmax_bits = __reduce_max_sync(mk, __float_as_uint(fmaxf(nf0, nf1)));
    float nmaxf = __uint_as_float(nmax_bits);

    // packed step direction * 0.1 (tolerance-loose path)
    u64 RS = pk2(rsq_ap(d2_0), rsq_ap(d2_1));
    u64 H = mul2(mul2(DX, RS), P01F_2);
    u64 G = mul2(mul2(DY, RS), P01F_2);

    // ---- packed coefficient pipeline ----------------------------------
    u64 C0 = fma2(P01, DY, mul2(P00, DX));
    u64 C1 = fma2(P11, DY, mul2(P10, DX));
    u64 C2 = fma2(P21, DY, mul2(P20, DX));

    u64 XX = mul2(X, X), XY = mul2(X, Y), YY = mul2(Y, Y);
    u64 HH = mul2(H, H), HG = mul2(H, G), GG = mul2(G, G);
    u64 c2yy = mul2(C2, YY);
    u64 c2gg = mul2(C2, GG);

    u64 K0 = mul2(X, fma2(C0, XX, fma2(C1, XY, c2yy)));
    u64 K3 = mul2(H, fma2(C0, HH, fma2(C1, HG, c2gg)));

    u64 C0_3 = add2(C0, add2(C0, C0));
    u64 C1_2 = add2(C1, C1);
    u64 C2_2 = add2(C2, C2);

    u64 gx0 = fma2(C0_3, XX, fma2(C1_2, XY, c2yy));
    u64 gy0 = fma2(C1, XX, mul2(C2_2, XY));
    u64 K1 = fma2(G, gy0, mul2(H, gx0));
    u64 gx1 = fma2(C0_3, HH, fma2(C1_2, HG, c2gg));
    u64 gy1 = fma2(C1, HH, mul2(C2_2, HG));
    u64 K2 = fma2(Y, gy1, mul2(X, gx1));

    // ---- seeds: single chain (4 packed ex2) ----------------------------
    const u64 THREE2 = 0x4040000040400000ULL;  // {3,3}
    const u64 SIX2   = 0x40C0000040C00000ULL;  // {6,6}
    const u64 L2008  = 0xC0693574C0693574ULL;  // {log2(0.08), log2(0.08)}

    u64 DG  = add2(K1, add2(K2, K3));               // dg(0) = k1+k2+k3
    u64 tt  = fma2(K3, THREE2, K2);
    u64 D2G = add2(tt, tt);                         // d2g(0) = 2k2+6k3
    u64 W6  = mul2(K3, SIX2);                       // 6k3

    u64 E = ex2_2(add2(K0, L2008));   // 0.08 * 2^{g(0)}
    u64 R = ex2_2(DG);                // r(0)
    u64 Q = ex2_2(D2G);               // q(0)
    u64 W = ex2_2(W6);

    // ---- single chain: s=0 folded; s=1..11 always; 12..14 vote-gated ---
    u64 acc = E;                       // s=0 (n >= 1 always)
#pragma unroll
    for (int s = 1; s <= 11; ++s) {
        E = mul2(E, R);                // e(s)
        if (s < 11) R = mul2(R, Q);    // r(s)
        if (s < 10) Q = mul2(Q, W);    // q(s)
        float m0 = __saturatef(nf0 - (float)s);  // exactly 1.0 or 0.0
        float m1 = __saturatef(nf1 - (float)s);
        acc = fma2(E, pk2(m0, m1), acc);
    }
    if (nmaxf > 12.0f) {               // some pair in warp needs step 12
        Q = mul2(Q, W);                // q10
        R = mul2(R, Q);                // r11
        E = mul2(E, R);                // e(12)
        float m0 = __saturatef(nf0 - 12.0f);
        float m1 = __saturatef(nf1 - 12.0f);
        acc = fma2(E, pk2(m0, m1), acc);
        if (nmaxf > 13.0f) {           // step 13
            Q = mul2(Q, W);            // q11
            R = mul2(R, Q);            // r12
            E = mul2(E, R);            // e(13)
            m0 = __saturatef(nf0 - 13.0f);
            m1 = __saturatef(nf1 - 13.0f);
            acc = fma2(E, pk2(m0, m1), acc);
            if (nmaxf > 14.0f) {       // step 14 (n == 15)
                Q = mul2(Q, W);        // q12
                R = mul2(R, Q);        // r13
                E = mul2(E, R);        // e(14)
                m0 = __saturatef(nf0 - 14.0f);
                m1 = __saturatef(nf1 - 14.0f);
                acc = fma2(E, pk2(m0, m1), acc);
            }
        }
    }

    float a0, a1;
    upk2(a0, a1, acc);
    float c0 = fmaf(0.02f, nf0, a0);
    float c1 = fmaf(0.02f, nf1, a1);

    if (full) {
        *reinterpret_cast<float2*>(out + base) = make_float2(c0, c1);
    } else {
        out[base] = c0;
    }
}

extern "C" void kernel_launch(void* const* d_in, const int* in_sizes, int n_in,
                              void* d_out, int out_size) {
    const float4* x1 = (const float4*)d_in[0];
    const float4* x2 = (const float4*)d_in[1];
    const float*  pp = (const float*)d_in[2];
    float* out = (float*)d_out;

    int n_pairs = out_size;
    int n_threads_total = (n_pairs + 1) / 2;
    int threads = 256;
    int blocks = (n_threads_total + threads - 1) / threads;
    flow_cost_kernel<<<blocks, threads>>>(x1, x2, pp, out, n_pairs);
}

// round 15
// speedup vs baseline: 1.0029x; 1.0029x over previous
#include <cuda_runtime.h>
#include <cstdint>

// FlowEmbedder cost, round 15: R13 body verbatim (best kernel, 9.12us),
// restructured to 4 pairs/thread (two independent packed pair-sets) to
// amortize per-thread fixed overhead (pp loads/folds/packs, indexing, vote,
// bounds ~= 32 slots) over 4 pairs instead of 2. One warp vote shared by
// both chains. No reg cap (caps spilled in R5/R7).
//
// cost_i = 0.02*n_i + sum_{s=0}^{n_i-1} 0.08 * 2^{g_i(s)}
//   g(s) = k0 + k1 s + k2 s^2 + k3 s^3   (k's include -log2(e))
//   e(s+1)=e(s)*r(s); r(s+1)=r(s)*q(s); q(s+1)=q(s)*w
//   seeds: e0=0.08*2^{k0}, r0=2^{k1+k2+k3}, q0=2^{2k2+6k3}, w=2^{6k3}
// n_i = floor(euc/0.1)+1 via bit-exact IEEE sqrt + correctly-rounded
// Markstein division (fl(1/0.1f)==10.0f exactly). Steps 12-14 vote-gated.

typedef unsigned long long u64;

__device__ __forceinline__ u64 pk2(float lo, float hi) {
    u64 r; asm("mov.b64 %0, {%1, %2};" : "=l"(r) : "f"(lo), "f"(hi)); return r;
}
__device__ __forceinline__ void upk2(float& lo, float& hi, u64 v) {
    asm("mov.b64 {%0, %1}, %2;" : "=f"(lo), "=f"(hi) : "l"(v));
}
__device__ __forceinline__ u64 mul2(u64 a, u64 b) {
    u64 d; asm("mul.rn.f32x2 %0, %1, %2;" : "=l"(d) : "l"(a), "l"(b)); return d;
}
__device__ __forceinline__ u64 add2(u64 a, u64 b) {
    u64 d; asm("add.rn.f32x2 %0, %1, %2;" : "=l"(d) : "l"(a), "l"(b)); return d;
}
__device__ __forceinline__ u64 fma2(u64 a, u64 b, u64 c) {
    u64 d; asm("fma.rn.f32x2 %0, %1, %2, %3;" : "=l"(d) : "l"(a), "l"(b), "l"(c)); return d;
}
__device__ __forceinline__ u64 ex2_2(u64 g) {
    float a, b; upk2(a, b, g);
    asm("ex2.approx.f32 %0, %1;" : "=f"(a) : "f"(a));
    asm("ex2.approx.f32 %0, %1;" : "=f"(b) : "f"(b));
    return pk2(a, b);
}
__device__ __forceinline__ float rsq_ap(float x) {
    float r; asm("rsqrt.approx.f32 %0, %1;" : "=f"(r) : "f"(x)); return r;
}

// R13 prologue: scalar per-pair head + packed coefficient pipeline.
// Produces packed cubic coefficients K0..K3 and per-lane nf.
__device__ __forceinline__ void prologue2(
    float ax0, float ay0, float bx0, float by0,
    float ax1, float ay1, float bx1, float by1,
    u64 P00, u64 P01, u64 P10, u64 P11, u64 P20, u64 P21,
    u64& K0, u64& K1, u64& K2, u64& K3, float& nf0, float& nf1)
{
    float dx0 = bx0 - ax0, dy0 = by0 - ay0;
    float dx1 = bx1 - ax1, dy1 = by1 - ay1;
    float d2_0 = fmaf(dx0, dx0, dy0 * dy0);
    float d2_1 = fmaf(dx1, dx1, dy1 * dy1);
    float euc0 = __fsqrt_rn(d2_0);
    float euc1 = __fsqrt_rn(d2_1);

    // correctly-rounded euc/0.1 (== __fdiv_rn, fl(1/0.1f)==10.0f exactly)
    float t0 = euc0 * 10.0f;
    nf0 = floorf(fmaf(fmaf(-0.1f, t0, euc0), 10.0f, t0)) + 1.0f;
    float t1 = euc1 * 10.0f;
    nf1 = floorf(fmaf(fmaf(-0.1f, t1, euc1), 10.0f, t1)) + 1.0f;

    float rs0 = rsq_ap(d2_0), rs1 = rsq_ap(d2_1);
    float h0 = (0.1f * dx0) * rs0, g0 = (0.1f * dy0) * rs0;
    float h1 = (0.1f * dx1) * rs1, g1 = (0.1f * dy1) * rs1;

    u64 DX = pk2(dx0, dx1), DY = pk2(dy0, dy1);
    u64 X = pk2(ax0, ax1), Y = pk2(ay0, ay1);
    u64 H = pk2(h0, h1), G = pk2(g0, g1);

    u64 C0 = fma2(P01, DY, mul2(P00, DX));
    u64 C1 = fma2(P11, DY, mul2(P10, DX));
    u64 C2 = fma2(P21, DY, mul2(P20, DX));

    u64 XX = mul2(X, X), XY = mul2(X, Y), YY = mul2(Y, Y);
    u64 HH = mul2(H, H), HG = mul2(H, G), GG = mul2(G, G);
    u64 c2yy = mul2(C2, YY);
    u64 c2gg = mul2(C2, GG);

    K0 = mul2(X, fma2(C0, XX, fma2(C1, XY, c2yy)));
    K3 = mul2(H, fma2(C0, HH, fma2(C1, HG, c2gg)));

    u64 C0_3 = add2(C0, add2(C0, C0));
    u64 C1_2 = add2(C1, C1);
    u64 C2_2 = add2(C2, C2);

    u64 gx0 = fma2(C0_3, XX, fma2(C1_2, XY, c2yy));
    u64 gy0 = fma2(C1, XX, mul2(C2_2, XY));
    K1 = fma2(G, gy0, mul2(H, gx0));
    u64 gx1 = fma2(C0_3, HH, fma2(C1_2, HG, c2gg));
    u64 gy1 = fma2(C1, HH, mul2(C2_2, HG));
    K2 = fma2(Y, gy1, mul2(X, gx1));
}

// R13 chain: single 15-step forward-difference product chain, s=0 folded,
// steps 12-14 gated by warp-uniform nmaxf.
__device__ __forceinline__ u64 chain15(u64 K0, u64 K1, u64 K2, u64 K3,
                                       float nf0, float nf1, float nmaxf)
{
    const u64 THREE2 = 0x4040000040400000ULL;  // {3,3}
    const u64 SIX2   = 0x40C0000040C00000ULL;  // {6,6}
    const u64 L2008  = 0xC0693574C0693574ULL;  // {log2(0.08), log2(0.08)}

    u64 DG  = add2(K1, add2(K2, K3));               // dg(0)
    u64 tt  = fma2(K3, THREE2, K2);
    u64 D2G = add2(tt, tt);                         // d2g(0)
    u64 W6  = mul2(K3, SIX2);                       // 6k3

    u64 E = ex2_2(add2(K0, L2008));   // 0.08 * 2^{g(0)}
    u64 R = ex2_2(DG);
    u64 Q = ex2_2(D2G);
    u64 W = ex2_2(W6);

    u64 acc = E;                       // s=0 (n >= 1 always)
#pragma unroll
    for (int s = 1; s <= 11; ++s) {
        E = mul2(E, R);                // e(s)
        if (s < 11) R = mul2(R, Q);
        if (s < 10) Q = mul2(Q, W);
        float m0 = __saturatef(nf0 - (float)s);  // exactly 1.0 or 0.0
        float m1 = __saturatef(nf1 - (float)s);
        acc = fma2(E, pk2(m0, m1), acc);
    }
    if (nmaxf > 12.0f) {
        Q = mul2(Q, W);                // q10
        R = mul2(R, Q);                // r11
        E = mul2(E, R);                // e(12)
        float m0 = __saturatef(nf0 - 12.0f);
        float m1 = __saturatef(nf1 - 12.0f);
        acc = fma2(E, pk2(m0, m1), acc);
        if (nmaxf > 13.0f) {
            Q = mul2(Q, W);            // q11
            R = mul2(R, Q);            // r12
            E = mul2(E, R);            // e(13)
            m0 = __saturatef(nf0 - 13.0f);
            m1 = __saturatef(nf1 - 13.0f);
            acc = fma2(E, pk2(m0, m1), acc);
            if (nmaxf > 14.0f) {
                Q = mul2(Q, W);        // q12
                R = mul2(R, Q);        // r13
                E = mul2(E, R);        // e(14)
                m0 = __saturatef(nf0 - 14.0f);
                m1 = __saturatef(nf1 - 14.0f);
                acc = fma2(E, pk2(m0, m1), acc);
            }
        }
    }
    return acc;
}

__global__ void __launch_bounds__(256)
flow_cost_kernel(const float4* __restrict__ x1,
                 const float4* __restrict__ x2,
                 const float* __restrict__ pp,
                 float* __restrict__ out,
                 int n_pairs) {
    int i = blockIdx.x * blockDim.x + threadIdx.x;  // 4 pairs per thread
    int base = 4 * i;
    if (base >= n_pairs) return;

    const float NL2E = -1.4426950408889634f;
    float p00 = NL2E * pp[0], p01 = NL2E * pp[1];
    float p10 = (3.0f * NL2E) * pp[2], p11 = (3.0f * NL2E) * pp[3];
    float p20 = (3.0f * NL2E) * pp[4], p21 = (3.0f * NL2E) * pp[5];
    u64 P00 = pk2(p00, p00), P01 = pk2(p01, p01);
    u64 P10 = pk2(p10, p10), P11 = pk2(p11, p11);
    u64 P20 = pk2(p20, p20), P21 = pk2(p21, p21);

    if (base + 3 < n_pairs) {
        // front-batched loads: MLP=4
        float4 aA = x1[2 * i];
        float4 aB = x1[2 * i + 1];
        float4 bA = x2[2 * i];
        float4 bB = x2[2 * i + 1];

        u64 K0a, K1a, K2a, K3a, K0b, K1b, K2b, K3b;
        float nf0, nf1, nf2, nf3;
        prologue2(aA.x, aA.y, bA.x, bA.y, aA.z, aA.w, bA.z, bA.w,
                  P00, P01, P10, P11, P20, P21,
                  K0a, K1a, K2a, K3a, nf0, nf1);
        prologue2(aB.x, aB.y, bB.x, bB.y, aB.z, aB.w, bB.z, bB.w,
                  P00, P01, P10, P11, P20, P21,
                  K0b, K1b, K2b, K3b, nf2, nf3);

        // one warp vote over all 4 pairs (positive floats order as uints)
        float nloc = fmaxf(fmaxf(nf0, nf1), fmaxf(nf2, nf3));
        unsigned mk = __activemask();
        float nmaxf = __uint_as_float(
            __reduce_max_sync(mk, __float_as_uint(nloc)));

        u64 accA = chain15(K0a, K1a, K2a, K3a, nf0, nf1, nmaxf);
        u64 accB = chain15(K0b, K1b, K2b, K3b, nf2, nf3, nmaxf);

        float a0, a1, a2, a3;
        upk2(a0, a1, accA);
        upk2(a2, a3, accB);
        float4 r;
        r.x = fmaf(0.02f, nf0, a0);
        r.y = fmaf(0.02f, nf1, a1);
        r.z = fmaf(0.02f, nf2, a2);
        r.w = fmaf(0.02f, nf3, a3);
        *reinterpret_cast<float4*>(out + base) = r;
    } else {
        // ragged tail: per-pair, lanes duplicated
        const float2* x1s = reinterpret_cast<const float2*>(x1);
        const float2* x2s = reinterpret_cast<const float2*>(x2);
        unsigned mk = __activemask();
        for (int p = base; p < n_pairs; ++p) {
            float2 a = x1s[p];
            float2 b = x2s[p];
            u64 K0, K1, K2, K3;
            float nf0, nf1;
            prologue2(a.x, a.y, b.x, b.y, a.x, a.y, b.x, b.y,
                      P00, P01, P10, P11, P20, P21,
                      K0, K1, K2, K3, nf0, nf1);
            float nmaxf = __uint_as_float(
                __reduce_max_sync(mk, __float_as_uint(nf0)));
            u64 acc = chain15(K0, K1, K2, K3, nf0, nf1, nmaxf);
            float a0, a1;
            upk2(a0, a1, acc);
            out[p] = fmaf(0.02f, nf0, a0);
        }
    }
}

extern "C" void kernel_launch(void* const* d_in, const int* in_sizes, int n_in,
                              void* d_out, int out_size) {
    const float4* x1 = (const float4*)d_in[0];
    const float4* x2 = (const float4*)d_in[1];
    const float*  pp = (const float*)d_in[2];
    float* out = (float*)d_out;

    int n_pairs = out_size;
    int n_threads_total = (n_pairs + 3) / 4;
    int threads = 256;
    int blocks = (n_threads_total + threads - 1) / threads;
    flow_cost_kernel<<<blocks, threads>>>(x1, x2, pp, out, n_pairs);
}